// round 17
// baseline (speedup 1.0000x reference)
#include <cuda_runtime.h>
#include <cstdint>

#define B 512
#define T 2048
#define K 32
#define CH 64             // time steps per staged chunk
#define NCH (T / CH)      // 32 chunks
#define WPC 4             // warps (batches) per CTA -> 1/SMSP, grid=128
#define CHB (CH * K * 4)  // pot chunk bytes = 8192
#define BPCH (CH * K)     // bp chunk bytes = 2048
#define FULL 0xffffffffu

// dynamic smem (bytes): pot[WPC][2][CH*K] f32 | bp[WPC][2][CH*K] u8 | st[WPC][K] f32
#define POT_BYTES (WPC * 2 * CH * K * 4)
#define BP_BYTES  (WPC * 2 * CH * K)
#define SMEM_DYN_BYTES (POT_BYTES + BP_BYTES + WPC * K * 4)

// backpointer trace: g_bp[b][t][j] = argmax_i(s_i(t-1)+T[i][j]), t=1..T-1
__device__ unsigned char g_bp[(size_t)B * T * K];

#define ADD2(out, a, b) asm("add.rn.f32x2 %0, %1, %2;" : "=l"(out) : "l"(a), "l"(b))
#define UNPK(lo, hi, v) asm("mov.b64 {%0, %1}, %2;" : "=f"(lo), "=f"(hi) : "l"(v))
#define WSYNC() __syncwarp()

__device__ __forceinline__ void cp16(uint32_t saddr, const void* gptr) {
    asm volatile("cp.async.cg.shared.global [%0], [%1], 16;" :: "r"(saddr), "l"(gptr));
}
#define CP_COMMIT()  asm volatile("cp.async.commit_group;")
#define CP_WAIT(n)   asm volatile("cp.async.wait_group %0;" :: "n"(n))

__device__ __forceinline__ void bulk_s2g(void* gdst, uint32_t ssrc, uint32_t bytes) {
    asm volatile("cp.async.bulk.global.shared::cta.bulk_group [%0], [%1], %2;"
                 :: "l"(gdst), "r"(ssrc), "r"(bytes) : "memory");
}
#define BULK_COMMIT()    asm volatile("cp.async.bulk.commit_group;")
#define BULK_WAIT_RD(n)  asm volatile("cp.async.bulk.wait_group.read %0;" :: "n"(n))
#define BULK_WAIT(n)     asm volatile("cp.async.bulk.wait_group %0;" :: "n"(n))
#define FENCE_ASYNC()    asm volatile("fence.proxy.async.shared::cta;" ::: "memory")

__global__ void __launch_bounds__(WPC * 32, 1) crf_viterbi_kernel(
    const float* __restrict__ pot,     // [B, T, K]
    const float* __restrict__ trans,   // [K, K]
    float* __restrict__ out)           // [B, T, K] one-hot
{
    extern __shared__ __align__(16) unsigned char dynb[];
    float* potBase        = (float*)dynb;
    unsigned char* bpBase = dynb + POT_BYTES;
    float* stBase         = (float*)(dynb + POT_BYTES + BP_BYTES);

    const int lane = threadIdx.x & 31;
    const int w    = threadIdx.x >> 5;
    const int b    = blockIdx.x * WPC + w;

    const char* pB = (const char*)(pot + (size_t)b * T * K);
    char* bpG      = (char*)(g_bp + (size_t)b * T * K);
    float* ob      = out + (size_t)b * T * K + lane;

    float* potW0 = potBase + (w * 2 + 0) * CH * K;
    float* potW1 = potBase + (w * 2 + 1) * CH * K;
    unsigned char* bpW0 = bpBase + (w * 2 + 0) * CH * K;
    unsigned char* bpW1 = bpBase + (w * 2 + 1) * CH * K;
    float* stW   = stBase + w * K;
    const uint32_t potA0 = (uint32_t)__cvta_generic_to_shared(potW0);
    const uint32_t potA1 = (uint32_t)__cvta_generic_to_shared(potW1);
    const uint32_t bpA0  = (uint32_t)__cvta_generic_to_shared(bpW0);
    const uint32_t bpA1  = (uint32_t)__cvta_generic_to_shared(bpW1);

    // packed transition column `lane`: tj2[q] = (trans[2q][lane], trans[2q+1][lane])
    unsigned long long tj2[16];
#pragma unroll
    for (int q = 0; q < 16; q++) {
        float lo = __ldg(trans + (2 * q) * K + lane);
        float hi = __ldg(trans + (2 * q + 1) * K + lane);
        asm("mov.b64 %0, {%1, %2};" : "=l"(tj2[q]) : "f"(lo), "f"(hi));
    }

    // zero the never-written bp row 0 of chunk 0 (flushed but unused)
    bpW0[lane] = 0;

    // ---- stage forward pot chunks 0 and 1 ----
#pragma unroll
    for (int i = 0; i < 16; i++)
        cp16(potA0 + lane * 16 + i * 512, pB + lane * 16 + i * 512);
    CP_COMMIT();
#pragma unroll
    for (int i = 0; i < 16; i++)
        cp16(potA1 + lane * 16 + i * 512, pB + CHB + lane * 16 + i * 512);
    CP_COMMIT();
    CP_WAIT(1);
    WSYNC();

    float s = potW0[lane];            // s(0) = pot(0)

// forward step: packed adds + max tree (chain), then tournament tree-walk for
// the first-index argmax (off-chain: 5 FSETP + 26 SEL, no serial OR chain).
// Equality walk: subtree-max == m  <=>  subtree contains an element == m.
#define FSTEP(pcurv, r, bprow) do {                                       \
        stW[lane] = s;                                                    \
        const ulonglong2* sp = (const ulonglong2*)stW;                    \
        unsigned long long v2[16];                                        \
        _Pragma("unroll")                                                 \
        for (int q = 0; q < 8; q++) {                                     \
            ulonglong2 rr = sp[q];                                        \
            ADD2(v2[2 * q],     rr.x, tj2[2 * q]);                        \
            ADD2(v2[2 * q + 1], rr.y, tj2[2 * q + 1]);                    \
        }                                                                 \
        float lov[16], m0[16];                                            \
        _Pragma("unroll")                                                 \
        for (int q = 0; q < 16; q++) {                                    \
            float lo, hi; UNPK(lo, hi, v2[q]);                            \
            lov[q] = lo;                                                  \
            m0[q] = fmaxf(lo, hi);                                        \
        }                                                                 \
        float m1[8];                                                      \
        _Pragma("unroll")                                                 \
        for (int q = 0; q < 8; q++) m1[q] = fmaxf(m0[2*q], m0[2*q+1]);    \
        float m2[4];                                                      \
        _Pragma("unroll")                                                 \
        for (int q = 0; q < 4; q++) m2[q] = fmaxf(m1[2*q], m1[2*q+1]);    \
        const float mA_ = fmaxf(m2[0], m2[1]);   /* max v[0..15]  */      \
        const float mB_ = fmaxf(mA_, m2[2]);                              \
        const float m   = fmaxf(mB_, m2[3]);                              \
        s = m + (pcurv);                                                  \
        /* ---- tree walk (first-index argmax), feeds only bp store ---- */ \
        const bool b4 = !(mA_ == m);                                      \
        const float c8 = b4 ? m2[2] : m2[0];                              \
        const bool b3 = !(c8 == m);                                       \
        const float s1_ = b4 ? m1[4] : m1[0];                             \
        const float s2_ = b4 ? m1[6] : m1[2];                             \
        const float c4 = b3 ? s2_ : s1_;                                  \
        const bool b2 = !(c4 == m);                                       \
        const float u1_ = b4 ? m0[8]  : m0[0];                            \
        const float u2_ = b4 ? m0[10] : m0[2];                            \
        const float u3_ = b4 ? m0[12] : m0[4];                            \
        const float u4_ = b4 ? m0[14] : m0[6];                            \
        const float w1_ = b3 ? u3_ : u1_;                                 \
        const float w2_ = b3 ? u4_ : u2_;                                 \
        const float c2 = b2 ? w2_ : w1_;                                  \
        const bool b1 = !(c2 == m);                                       \
        const float x1_ = b4 ? lov[8]  : lov[0];                          \
        const float x2_ = b4 ? lov[9]  : lov[1];                          \
        const float x3_ = b4 ? lov[10] : lov[2];                          \
        const float x4_ = b4 ? lov[11] : lov[3];                          \
        const float x5_ = b4 ? lov[12] : lov[4];                          \
        const float x6_ = b4 ? lov[13] : lov[5];                          \
        const float x7_ = b4 ? lov[14] : lov[6];                          \
        const float x8_ = b4 ? lov[15] : lov[7];                          \
        const float y1_ = b3 ? x5_ : x1_;                                 \
        const float y2_ = b3 ? x6_ : x2_;                                 \
        const float y3_ = b3 ? x7_ : x3_;                                 \
        const float y4_ = b3 ? x8_ : x4_;                                 \
        const float z1_ = b2 ? y3_ : y1_;                                 \
        const float z2_ = b2 ? y4_ : y2_;                                 \
        const float c1 = b1 ? z2_ : z1_;                                  \
        const bool b0 = !(c1 == m);                                       \
        const int idx = ((int)b4 << 4) | ((int)b3 << 3) | ((int)b2 << 2)  \
                      | ((int)b1 << 1) | (int)b0;                         \
        (bprow)[(r) * K + lane] = (unsigned char)idx;                     \
    } while (0)

    // ================= forward =================
    // chunk 0 (rows 1..CH-1), peeled
    {
        float pcpre = potW0[1 * K + lane];
#pragma unroll 16
        for (int r = 1; r < CH; r++) {
            const float pcur = pcpre;
            const int rn = (r < CH - 1) ? r + 1 : r;
            pcpre = potW0[rn * K + lane];
            FSTEP(pcur, r, bpW0);
        }
        WSYNC();
        FENCE_ASYNC();
        if (lane == 0) {
            bulk_s2g((void*)bpG, bpA0, BPCH);
            BULK_COMMIT();
            BULK_WAIT_RD(1);
        }
        const char* src = pB + 2 * (size_t)CHB;
#pragma unroll
        for (int i = 0; i < 16; i++)
            cp16(potA0 + lane * 16 + i * 512, src + lane * 16 + i * 512);
        CP_COMMIT();
        CP_WAIT(1);
        WSYNC();
    }
    for (int c = 1; c < NCH; c++) {
        const float* pc      = (c & 1) ? potW1 : potW0;
        unsigned char* bprow = (c & 1) ? bpW1 : bpW0;
        float pcpre = pc[lane];
#pragma unroll 16
        for (int r = 0; r < CH; r++) {
            const float pcur = pcpre;
            const int rn = (r < CH - 1) ? r + 1 : r;
            pcpre = pc[rn * K + lane];
            FSTEP(pcur, r, bprow);
        }
        WSYNC();
        if (c <= NCH - 3) {                       // last 2 bp chunks stay resident
            FENCE_ASYNC();
            if (lane == 0) {
                bulk_s2g((void*)(bpG + (size_t)c * BPCH), (c & 1) ? bpA1 : bpA0, BPCH);
                BULK_COMMIT();
                BULK_WAIT_RD(1);
            }
        }
        if (c + 2 < NCH) {
            const uint32_t dst = ((c & 1) == 0) ? potA0 : potA1;
            const char* src = pB + (size_t)(c + 2) * CHB;
#pragma unroll
            for (int i = 0; i < 16; i++)
                cp16(dst + lane * 16 + i * 512, src + lane * 16 + i * 512);
            CP_COMMIT();
            CP_WAIT(1);
            WSYNC();
        } else if (c + 1 < NCH) {
            CP_WAIT(0);
            WSYNC();
        }
    }

    // ---- final tag: first-index argmax over lanes of s(T-1) ----
    float mm = s;
#pragma unroll
    for (int off = 16; off; off >>= 1) mm = fmaxf(mm, __shfl_xor_sync(FULL, mm, off));
    int tag = __ffs(__ballot_sync(FULL, s == mm)) - 1;
    ob[(size_t)(T - 1) * K] = (lane == tag) ? 1.0f : 0.0f;

    // bp bulk stores must be globally visible before cp.async re-reads
    if (lane == 0) BULK_WAIT(0);
    WSYNC();

    // ================= backtrack: pure bp pointer chase =================
    // chunks NCH-1 (buf1) and NCH-2 (buf0) still resident.

#define CSTEP(t, r, bpc) do {                                             \
        tag = (int)(bpc)[(r) * K + tag];                                  \
        ob[(size_t)((t) - 1) * K] = (lane == tag) ? 1.0f : 0.0f;          \
    } while (0)

#define STAGE_BP(c) do {                                                  \
        const uint32_t bd = (((c) & 1) == 0) ? bpA0 : bpA1;               \
        const char* gb = bpG + (size_t)((c) - 2) * BPCH;                  \
        _Pragma("unroll")                                                 \
        for (int i = 0; i < 4; i++) cp16(bd + lane*16 + i*512, gb + lane*16 + i*512); \
        CP_COMMIT();                                                      \
        CP_WAIT(1);                                                       \
        WSYNC();                                                          \
    } while (0)

    // chunk NCH-1: t = T-1 .. (NCH-1)*CH  (rows CH-1..0)
    {
#pragma unroll 16
        for (int r = CH - 1; r >= 0; r--) CSTEP((NCH - 1) * CH + r, r, bpW1);
        STAGE_BP(NCH - 1);
    }
    for (int c = NCH - 2; c >= 1; c--) {
        const unsigned char* bpc = (c & 1) ? bpW1 : bpW0;
#pragma unroll 16
        for (int r = CH - 1; r >= 0; r--) CSTEP(c * CH + r, r, bpc);
        if (c >= 2) {
            STAGE_BP(c);
        } else {
            CP_WAIT(0);
            WSYNC();
        }
    }
    // chunk 0: t = CH-1 .. 1 (row 0 is t=0, no bp)
    {
#pragma unroll 16
        for (int r = CH - 1; r >= 1; r--) CSTEP(r, r, bpW0);
    }
}

extern "C" void kernel_launch(void* const* d_in, const int* in_sizes, int n_in,
                              void* d_out, int out_size)
{
    const float* pot   = (const float*)d_in[0];
    const float* trans = (const float*)d_in[1];
    float* outp        = (float*)d_out;
    cudaFuncSetAttribute(crf_viterbi_kernel,
                         cudaFuncAttributeMaxDynamicSharedMemorySize, SMEM_DYN_BYTES);
    crf_viterbi_kernel<<<B / WPC, WPC * 32, SMEM_DYN_BYTES>>>(pot, trans, outp);
}